// round 2
// baseline (speedup 1.0000x reference)
#include <cuda_runtime.h>

// ---------------------------------------------------------------------------
// GraphRNNDecoder: autoregressive LSTM rollout.
//   N=4096 rows, T=128 steps, D=4, H=256, gates 4H=1024.
// Persistent kernel: 128 CTAs x 1024 threads, each CTA owns 32 rows and loops
// all T steps locally (rows are independent -> no inter-CTA sync needed).
// fp32 math via packed fma.rn.f32x2 (rows paired in 64-bit regs).
// ---------------------------------------------------------------------------

#define T_STEPS 128
#define DIN     4
#define HID     256
#define G4      1024      // 4*HID
#define MROWS   32        // rows per CTA
#define NCTA    128       // 4096 / 32
#define KC      64        // 256 / 4 k-chunks

// k-chunk packed weights: [kc][j] -> float4 of W[j][4kc..4kc+3]
__device__ float4 g_whh[KC * G4];   // 1 MB
__device__ float4 g_fc1[KC * HID];  // 256 KB
__device__ float4 g_fc2[KC * HID];  // 256 KB

__global__ void pack_kernel(const float* __restrict__ W_hh,
                            const float* __restrict__ fc1_w,
                            const float* __restrict__ fc2_w) {
    int i = blockIdx.x * blockDim.x + threadIdx.x;
    if (i < KC * G4) {
        int kc = i >> 10, j = i & 1023;
        g_whh[i] = *reinterpret_cast<const float4*>(W_hh + j * HID + kc * 4);
    }
    if (i < KC * HID) {
        int kc = i >> 8, j = i & 255;
        g_fc1[i] = *reinterpret_cast<const float4*>(fc1_w + j * HID + kc * 4);
        g_fc2[i] = *reinterpret_cast<const float4*>(fc2_w + j * HID + kc * 4);
    }
}

// ---- packed f32x2 helpers --------------------------------------------------
__device__ __forceinline__ unsigned long long pk2(float lo, float hi) {
    unsigned long long r;
    asm("mov.b64 %0, {%1, %2};" : "=l"(r) : "f"(lo), "f"(hi));
    return r;
}
__device__ __forceinline__ void fma2(unsigned long long& d,
                                     unsigned long long a,
                                     unsigned long long b) {
    asm("fma.rn.f32x2 %0, %1, %2, %0;" : "+l"(d) : "l"(a), "l"(b));
}
__device__ __forceinline__ void unpk2(unsigned long long v, float& lo, float& hi) {
    asm("mov.b64 {%0, %1}, %2;" : "=f"(lo), "=f"(hi) : "l"(v));
}

__device__ __forceinline__ float sigf(float x) {
    return __fdividef(1.0f, 1.0f + __expf(-x));
}
__device__ __forceinline__ float tanhf_fast(float x) {
    float e = __expf(2.0f * x);
    return 1.0f - __fdividef(2.0f, e + 1.0f);
}

// ---- shared layout (floats) ------------------------------------------------
// gates:  [1024][33]   33792   (aliased: p1 at 0, p2 at 9216 within this region)
// hsh:    [256][36]     9216   at 33792   (k-major hidden state, float4-aligned rows)
// csh:    [256][33]     8448   at 43008
// prevsh: [32][4]        128   at 51456
// fc3sh:  [4][256]      1024   at 51584
// b3sh:   [4]              4   at 52608
#define OFF_GATES 0
#define OFF_P1    0
#define OFF_P2    9216
#define OFF_H     33792
#define OFF_C     43008
#define OFF_PREV  51456
#define OFF_FC3   51584
#define OFF_B3    52608
#define SMEM_FLOATS 52612
#define SMEM_BYTES  (SMEM_FLOATS * 4)

// FC GEMM: dst[j][r] = relu(bias + sum_k src[k][r] * W[j][k]) for 8 rows r0..r0+7
__device__ __forceinline__ void fc_gemm(const float* __restrict__ src,
                                        float* __restrict__ dst,
                                        const float4* __restrict__ wp,
                                        float bias, int j2, int r0) {
    unsigned long long acc[4];
    unsigned long long bb = pk2(bias, bias);
#pragma unroll
    for (int p = 0; p < 4; p++) acc[p] = bb;

#pragma unroll 4
    for (int kc = 0; kc < KC; kc++) {
        float4 w = wp[kc * HID + j2];
        unsigned long long w0 = pk2(w.x, w.x), w1 = pk2(w.y, w.y);
        unsigned long long w2v = pk2(w.z, w.z), w3 = pk2(w.w, w.w);
        const float* sb = src + kc * 4 * 36 + r0;
#pragma unroll
        for (int g = 0; g < 2; g++) {
            ulonglong2 h0 = *reinterpret_cast<const ulonglong2*>(sb + 0 * 36 + 4 * g);
            fma2(acc[2 * g], w0, h0.x); fma2(acc[2 * g + 1], w0, h0.y);
            ulonglong2 h1 = *reinterpret_cast<const ulonglong2*>(sb + 1 * 36 + 4 * g);
            fma2(acc[2 * g], w1, h1.x); fma2(acc[2 * g + 1], w1, h1.y);
            ulonglong2 h2 = *reinterpret_cast<const ulonglong2*>(sb + 2 * 36 + 4 * g);
            fma2(acc[2 * g], w2v, h2.x); fma2(acc[2 * g + 1], w2v, h2.y);
            ulonglong2 h3 = *reinterpret_cast<const ulonglong2*>(sb + 3 * 36 + 4 * g);
            fma2(acc[2 * g], w3, h3.x); fma2(acc[2 * g + 1], w3, h3.y);
        }
    }
#pragma unroll
    for (int p = 0; p < 4; p++) {
        float lo, hi; unpk2(acc[p], lo, hi);
        dst[j2 * 36 + r0 + 2 * p]     = fmaxf(lo, 0.0f);
        dst[j2 * 36 + r0 + 2 * p + 1] = fmaxf(hi, 0.0f);
    }
}

__global__ void __launch_bounds__(1024, 1)
rnn_rollout_kernel(const float* __restrict__ inputs,
                   const float* __restrict__ W_ih,
                   const float* __restrict__ b_ih,
                   const float* __restrict__ b_hh,
                   const float* __restrict__ fc1_b,
                   const float* __restrict__ fc2_b,
                   const float* __restrict__ fc3_w,
                   const float* __restrict__ fc3_b,
                   float* __restrict__ out) {
    extern __shared__ float smem[];
    float* gates  = smem + OFF_GATES;   // [1024][33]
    float* p1     = smem + OFF_P1;      // [256][36]
    float* p2     = smem + OFF_P2;      // [256][36]
    float* hsh    = smem + OFF_H;       // [256][36]
    float* csh    = smem + OFF_C;       // [256][33]
    float* prevsh = smem + OFF_PREV;    // [32][4]
    float* fc3sh  = smem + OFF_FC3;     // [4][256]
    float* b3sh   = smem + OFF_B3;      // [4]

    const int tid  = threadIdx.x;
    const int j2   = tid & 255;     // hidden unit for elementwise / fc phases
    const int rg   = tid >> 8;      // row group 0..3
    const int r0   = rg * 8;        // 8 rows per thread in elementwise / fc
    const int row0 = blockIdx.x * MROWS;

    // persistent per-thread constants
    const float bias_g = b_ih[tid] + b_hh[tid];
    const float4 wih   = *reinterpret_cast<const float4*>(W_ih + tid * DIN);
    const float fb1    = fc1_b[j2];
    const float fb2    = fc2_b[j2];

    // ---- init shared state ----
    for (int i = tid; i < HID * 36; i += 1024) hsh[i] = 0.0f;
    for (int i = tid; i < HID * 33; i += 1024) csh[i] = 0.0f;
    if (tid < G4) fc3sh[tid] = fc3_w[tid];
    if (tid < DIN) b3sh[tid] = fc3_b[tid];
    if (tid < MROWS * DIN) {
        int n = tid >> 2, d = tid & 3;
        prevsh[tid] = inputs[((size_t)(row0 + n) * T_STEPS) * DIN + d];
    }
    __syncthreads();

    for (int t = 0; t < T_STEPS; t++) {
        // ---- phase A: gate GEMM. thread tid = gate unit j, two passes of 16 rows
        const float4* wp = g_whh;
#pragma unroll
        for (int rh = 0; rh < 2; rh++) {
            const int n0 = rh * 16;
            unsigned long long acc[8];
#pragma unroll
            for (int p = 0; p < 8; p++) {
                const float4 pa = *reinterpret_cast<const float4*>(&prevsh[(n0 + 2 * p) * 4]);
                const float4 pb = *reinterpret_cast<const float4*>(&prevsh[(n0 + 2 * p + 1) * 4]);
                float sa = bias_g + wih.x * pa.x + wih.y * pa.y + wih.z * pa.z + wih.w * pa.w;
                float sb = bias_g + wih.x * pb.x + wih.y * pb.y + wih.z * pb.z + wih.w * pb.w;
                acc[p] = pk2(sa, sb);
            }
#pragma unroll 4
            for (int kc = 0; kc < KC; kc++) {
                float4 w = wp[kc * G4 + tid];
                unsigned long long w0 = pk2(w.x, w.x), w1 = pk2(w.y, w.y);
                unsigned long long w2v = pk2(w.z, w.z), w3 = pk2(w.w, w.w);
                const float* hb = hsh + kc * 4 * 36 + n0;
#pragma unroll
                for (int g = 0; g < 4; g++) {
                    ulonglong2 h0 = *reinterpret_cast<const ulonglong2*>(hb + 0 * 36 + 4 * g);
                    fma2(acc[2 * g], w0, h0.x); fma2(acc[2 * g + 1], w0, h0.y);
                    ulonglong2 h1 = *reinterpret_cast<const ulonglong2*>(hb + 1 * 36 + 4 * g);
                    fma2(acc[2 * g], w1, h1.x); fma2(acc[2 * g + 1], w1, h1.y);
                    ulonglong2 h2 = *reinterpret_cast<const ulonglong2*>(hb + 2 * 36 + 4 * g);
                    fma2(acc[2 * g], w2v, h2.x); fma2(acc[2 * g + 1], w2v, h2.y);
                    ulonglong2 h3 = *reinterpret_cast<const ulonglong2*>(hb + 3 * 36 + 4 * g);
                    fma2(acc[2 * g], w3, h3.x); fma2(acc[2 * g + 1], w3, h3.y);
                }
            }
#pragma unroll
            for (int p = 0; p < 8; p++) {
                float lo, hi; unpk2(acc[p], lo, hi);
                gates[tid * 33 + n0 + 2 * p]     = lo;
                gates[tid * 33 + n0 + 2 * p + 1] = hi;
            }
        }
        __syncthreads();

        // ---- phase B: LSTM elementwise. thread (j2, rows r0..r0+7)
#pragma unroll
        for (int r = 0; r < 8; r++) {
            const int n = r0 + r;
            float gi = gates[j2 * 33 + n];
            float gf = gates[(j2 + 256) * 33 + n];
            float gg = gates[(j2 + 512) * 33 + n];
            float go = gates[(j2 + 768) * 33 + n];
            float c  = sigf(gf) * csh[j2 * 33 + n] + sigf(gi) * tanhf_fast(gg);
            csh[j2 * 33 + n] = c;
            hsh[j2 * 36 + n] = sigf(go) * tanhf_fast(c);
        }
        __syncthreads();

        // ---- phase C: fc1 (h -> p1, relu)
        fc_gemm(hsh, p1, g_fc1, fb1, j2, r0);
        __syncthreads();

        // ---- phase D: fc2 (p1 -> p2, relu)
        fc_gemm(p1, p2, g_fc2, fb2, j2, r0);
        __syncthreads();

        // ---- phase E: fc3 + residual + output
        if (tid < MROWS * DIN) {
            const int n = tid >> 2, d = tid & 3;
            float acc = b3sh[d] + prevsh[tid];
            const float* f3 = fc3sh + d * HID;
            const float* pp = p2 + n;
#pragma unroll 8
            for (int k = 0; k < HID; k++) acc += pp[k * 36] * f3[k];
            out[((size_t)(row0 + n) * T_STEPS + t) * DIN + d] = acc;
            prevsh[tid] = acc;
        }
        __syncthreads();
    }
}

extern "C" void kernel_launch(void* const* d_in, const int* in_sizes, int n_in,
                              void* d_out, int out_size) {
    const float* inputs = (const float*)d_in[0];
    const float* W_ih   = (const float*)d_in[1];
    const float* W_hh   = (const float*)d_in[2];
    const float* b_ih   = (const float*)d_in[3];
    const float* b_hh   = (const float*)d_in[4];
    const float* fc1_w  = (const float*)d_in[5];
    const float* fc1_b  = (const float*)d_in[6];
    const float* fc2_w  = (const float*)d_in[7];
    const float* fc2_b  = (const float*)d_in[8];
    const float* fc3_w  = (const float*)d_in[9];
    const float* fc3_b  = (const float*)d_in[10];
    float* out = (float*)d_out;

    pack_kernel<<<64, 1024>>>(W_hh, fc1_w, fc2_w);

    cudaFuncSetAttribute(rnn_rollout_kernel,
                         cudaFuncAttributeMaxDynamicSharedMemorySize, SMEM_BYTES);
    rnn_rollout_kernel<<<NCTA, 1024, SMEM_BYTES>>>(
        inputs, W_ih, b_ih, b_hh, fc1_b, fc2_b, fc3_w, fc3_b, out);
}